// round 8
// baseline (speedup 1.0000x reference)
#include <cuda_runtime.h>
#include <math.h>
#include <stdint.h>

#define T_LEN 8192
#define T4 (T_LEN / 4)            // 2048 float4s
#define RADIUS 12                 // truncation rel-err ~9e-5 << 1e-3
#define NTAPS (RADIUS + 1)        // 13 one-sided taps incl. x=0
#define CLUSTER 8
#define THREADS 256
#define OPT 4
#define PER_CTA (THREADS * OPT)   // 1024
#define INV_SQRT_2PI 0.39894228f
#define NOISE_SIGMA 0.01f

__device__ __forceinline__ uint32_t smem_u32(const void* p) {
    uint32_t a;
    asm("{ .reg .u64 t; cvta.to.shared.u64 t, %1; cvt.u32.u64 %0, t; }"
        : "=r"(a) : "l"(p));
    return a;
}
__device__ __forceinline__ void warp_sum2(float& a, float& b) {
    #pragma unroll
    for (int o = 16; o > 0; o >>= 1) {
        a += __shfl_xor_sync(0xffffffffu, a, o);
        b += __shfl_xor_sync(0xffffffffu, b, o);
    }
}

__global__ void __launch_bounds__(THREADS, 1) __cluster_dims__(CLUSTER, 1, 1)
k_fused(const float4* __restrict__ X4,
        const float* __restrict__ weight,
        const float* __restrict__ sigma_min,
        const float* __restrict__ sigma_max,
        const float4* __restrict__ noise4,
        float4* __restrict__ out4) {
    __shared__ float sG[NTAPS];
    __shared__ float spmn[8], spmx[8];
    __shared__ __align__(8) float2 slot[CLUSTER];      // {lo,hi} from each CTA
    __shared__ __align__(8) unsigned long long mbar;   // arrival barrier, count=8

    const int tid = threadIdx.x;
    const int wid = tid >> 5;                  // 0..7
    const int lid = tid & 31;
    uint32_t rank;
    asm("mov.u32 %0, %%cluster_ctarank;" : "=r"(rank));
    const int vbase = (int)rank * (PER_CTA / 4);
    const uint32_t mbar_a = smem_u32(&mbar);

    // ---- mbarrier init; early cluster arrive (release: init visible to peers) ----
    if (tid == 0)
        asm volatile("mbarrier.init.shared.b64 [%0], %1;" :: "r"(mbar_a), "r"(CLUSTER) : "memory");
    __syncthreads();
    asm volatile("barrier.cluster.arrive.aligned;" ::: "memory");

    // ---- long-latency loads: weight first (heads the longest chain) ----
    float w0 = weight[lid];
    float w1 = weight[lid + 32];
    float w2 = weight[lid + 64];
    float w3 = weight[lid + 96];
    float smn_v = sigma_min[0];
    float smx_v = sigma_max[0];
    float4 nz4 = noise4[vbase + tid];

    // per-thread mask window: X is exactly {0,1}, no conversion needed.
    // wr[m] = X[4*(vbase+tid) - 16 + m], m = 0..31 (8 predicated LDG.128)
    float wr[32];
    {
        #pragma unroll
        for (int k = 0; k < 8; ++k) {
            int g = vbase + tid - 4 + k;
            float4 v = make_float4(0.f, 0.f, 0.f, 0.f);
            if (g >= 0 && g < T4) v = X4[g];
            wr[4 * k + 0] = v.x; wr[4 * k + 1] = v.y;
            wr[4 * k + 2] = v.z; wr[4 * k + 3] = v.w;
        }
    }

    // ---- sG: warp wid -> taps wid and wid+8 (warps 0..4), 4 sigmas/lane ----
    {
        float e0 = __expf(w0), e1 = __expf(w1), e2 = __expf(w2), e3 = __expf(w3);

        float step = (smx_v - smn_v) * (1.0f / 127.0f);
        float s0 = fabsf(smn_v + (float)lid * step);
        float s1 = fabsf(smn_v + (float)(lid + 32) * step);
        float s2 = fabsf(smn_v + (float)(lid + 64) * step);
        float s3 = fabsf(smn_v + (float)(lid + 96) * step);
        float a0 = e0 * INV_SQRT_2PI / s0, c0 = 0.5f / (s0 * s0);
        float a1 = e1 * INV_SQRT_2PI / s1, c1 = 0.5f / (s1 * s1);
        float a2 = e2 * INV_SQRT_2PI / s2, c2 = 0.5f / (s2 * s2);
        float a3 = e3 * INV_SQRT_2PI / s3, c3 = 0.5f / (s3 * s3);

        float xx0 = (float)wid;       xx0 *= xx0;
        float xx1 = (float)(wid + 8); xx1 *= xx1;
        float v0 = a0 * __expf(-xx0 * c0) + a1 * __expf(-xx0 * c1)
                 + a2 * __expf(-xx0 * c2) + a3 * __expf(-xx0 * c3);
        float v1 = a0 * __expf(-xx1 * c0) + a1 * __expf(-xx1 * c1)
                 + a2 * __expf(-xx1 * c2) + a3 * __expf(-xx1 * c3);

        warp_sum2(v0, v1);
        float denom = e0 + e1 + e2 + e3;
        #pragma unroll
        for (int o = 16; o > 0; o >>= 1)
            denom += __shfl_xor_sync(0xffffffffu, denom, o);

        if (lid == 0) {
            float rden = __fdividef(1.0f, denom);
            sG[wid] = v0 * rden;
            if (wid < NTAPS - 8) sG[wid + 8] = v1 * rden;
        }
    }
    __syncthreads();                           // sG ready (only sync in kernel)

    float c[NTAPS];
    #pragma unroll
    for (int x = 0; x < NTAPS; ++x) c[x] = sG[x];

    // ---- conv: 4 outputs/thread from the register window ----
    float acc[OPT];
    {
        float nzs[4] = {nz4.x, nz4.y, nz4.z, nz4.w};
        #pragma unroll
        for (int j = 0; j < OPT; ++j) {
            float a0 = fmaf(c[0], wr[15 + j], NOISE_SIGMA * nzs[j]);
            float a1 = 0.0f;
            #pragma unroll
            for (int x = 1; x < NTAPS; x += 2) {
                a0 = fmaf(c[x], wr[15 + j - x] + wr[15 + j + x], a0);
                if (x + 1 < NTAPS)
                    a1 = fmaf(c[x + 1], wr[14 + j - x] + wr[16 + j + x], a1);
            }
            acc[j] = a0 + a1;
        }
    }

    // ---- cluster.wait (long since satisfied) before any remote DSMEM op ----
    asm volatile("barrier.cluster.wait.aligned;" ::: "memory");

    // ---- min/max: thread -> warp -> block ----
    float mn = fminf(fminf(acc[0], acc[1]), fminf(acc[2], acc[3]));
    float mx = fmaxf(fmaxf(acc[0], acc[1]), fmaxf(acc[2], acc[3]));
    #pragma unroll
    for (int o = 16; o > 0; o >>= 1) {
        mn = fminf(mn, __shfl_xor_sync(0xffffffffu, mn, o));
        mx = fmaxf(mx, __shfl_xor_sync(0xffffffffu, mx, o));
    }
    if (lid == 0) { spmn[wid] = mn; spmx[wid] = mx; }
    __syncthreads();

    if (wid == 0) {
        float bmn = spmn[lid & 7];
        float bmx = spmx[lid & 7];
        #pragma unroll
        for (int o = 4; o > 0; o >>= 1) {
            bmn = fminf(bmn, __shfl_xor_sync(0xffffffffu, bmn, o));
            bmx = fmaxf(bmx, __shfl_xor_sync(0xffffffffu, bmx, o));
        }
        if (lid < CLUSTER) {
            // lane lid: packed {lo,hi} store into peer lid's slot[rank], then
            // release-arrive on peer lid's mbarrier (orders the store).
            uint32_t a = smem_u32(&slot[rank]);
            uint32_t rs, rb;
            asm volatile("mapa.shared::cluster.u32 %0, %1, %2;"
                         : "=r"(rs) : "r"(a), "r"(lid));
            asm volatile("mapa.shared::cluster.u32 %0, %1, %2;"
                         : "=r"(rb) : "r"(mbar_a), "r"(lid));
            unsigned long long pk =
                ((unsigned long long)__float_as_uint(bmx) << 32) | __float_as_uint(bmn);
            asm volatile("st.shared::cluster.u64 [%0], %1;" :: "r"(rs), "l"(pk) : "memory");
            asm volatile("mbarrier.arrive.release.cluster.shared::cluster.b64 _, [%0];"
                         :: "r"(rb) : "memory");
        }
    }

    // ---- wait for all 8 arrivals (phase 0; smem fresh every launch) ----
    {
        uint32_t done;
        asm volatile(
            "{\n\t.reg .pred p;\n\t"
            "mbarrier.try_wait.parity.acquire.cluster.shared::cta.b64 p, [%1], %2;\n\t"
            "selp.b32 %0, 1, 0, p;\n\t}"
            : "=r"(done) : "r"(mbar_a), "r"(0) : "memory");
        if (!done) {
            asm volatile(
                "{\n\t.reg .pred P1;\n\t"
                "W%=:\n\t"
                "mbarrier.try_wait.parity.acquire.cluster.shared::cta.b64 P1, [%0], %1;\n\t"
                "@P1 bra.uni D%=;\n\t"
                "bra.uni W%=;\n\t"
                "D%=:\n\t}"
                :: "r"(mbar_a), "r"(0) : "memory");
        }
    }

    float L = slot[0].x, H = slot[0].y;
    #pragma unroll
    for (int j = 1; j < CLUSTER; ++j) {
        L = fminf(L, slot[j].x);
        H = fmaxf(H, slot[j].y);
    }
    float inv = __fdividef(1.0f, H - L);
    out4[vbase + tid] = make_float4((acc[0] - L) * inv, (acc[1] - L) * inv,
                                    (acc[2] - L) * inv, (acc[3] - L) * inv);
}

extern "C" void kernel_launch(void* const* d_in, const int* in_sizes, int n_in,
                              void* d_out, int out_size) {
    const float4* X4  = (const float4*)d_in[0];
    const float* wgt  = (const float*)d_in[1];
    const float* smin = (const float*)d_in[2];
    const float* smax = (const float*)d_in[3];
    const float4* nz4 = (const float4*)d_in[4];
    float4* out4 = (float4*)d_out;

    k_fused<<<CLUSTER, THREADS>>>(X4, wgt, smin, smax, nz4, out4);
}